// round 3
// baseline (speedup 1.0000x reference)
#include <cuda_runtime.h>
#include <math.h>

#define NN 8192
#define NE 131072

#define IS128 0.08838834764831845f
#define IS10  0.31622776601683794f
#define IS264 0.06154574548966636f
#define IS256 0.0625f
#define INV8  0.125f
#define INV_SQRT3 0.57735026918962576f

// ---------------- scratch (no allocation allowed) ----------------
__device__ float g_us[NN*128];
__device__ float g_uv[NN*384];
__device__ float g_src[NN*128];
__device__ float g_tgt[NN*128];
__device__ float g_hA[(size_t)NE*64];
__device__ float g_hB[(size_t)NE*64];
__device__ float g_density[NN];
__device__ float g_msgs[NN*256];
__device__ float g_msgv[NN*768];

__device__ __forceinline__ float siluf(float x){ return x/(1.0f+expf(-x)); }
__device__ __forceinline__ float sigmf(float x){ return 1.0f/(1.0f+expf(-x)); }

// ---------------- K0: zero the accumulators ----------------
__global__ void k0_zero(){
    size_t idx = (size_t)blockIdx.x*blockDim.x + threadIdx.x;
    const size_t n1 = (size_t)NN*256, n2 = (size_t)NN*768;
    if (idx < n1) g_msgs[idx] = 0.f;
    else if (idx < n1+n2) g_msgv[idx-n1] = 0.f;
    else if (idx < n1+n2+NN) g_density[idx-n1-n2] = 0.f;
}

// ---------------- K1: node prep (sc, us, uv, src_e, tgt_e) ----------------
__global__ __launch_bounds__(128) void k1_node_prep(
    const float* __restrict__ node_attrs, const float* __restrict__ node_feats,
    const float* __restrict__ Wss, const float* __restrict__ Wsv,
    const float* __restrict__ Wus, const float* __restrict__ Wuv,
    const float* __restrict__ Wsrc, const float* __restrict__ Wtgt,
    float* __restrict__ out_sc)
{
    __shared__ float s8[8][128];
    __shared__ float v8[8][384];
    __shared__ float a8[8][10];
    int nb = blockIdx.x*8;
    int tid = threadIdx.x;
    for (int idx=tid; idx<8*512; idx+=128){
        int i = idx>>9, f = idx&511;
        float v = node_feats[(size_t)(nb+i)*512 + f];
        if (f<128) s8[i][f]=v; else v8[i][f-128]=v;
    }
    for (int idx=tid; idx<80; idx+=128)
        a8[idx/10][idx%10] = node_attrs[(size_t)(nb + idx/10)*10 + (idx%10)];
    __syncthreads();
    int w = tid;
    float acc1[8], acc2[8];

    // scalar channels: us = s@W_up_s, sc_s = s@W_skip_s
    #pragma unroll
    for (int i=0;i<8;i++){acc1[i]=0.f;acc2[i]=0.f;}
    for (int k=0;k<128;k++){
        float wu = Wus[k*128+w], ws = Wss[k*128+w];
        #pragma unroll
        for (int i=0;i<8;i++){ float sv=s8[i][k]; acc1[i]+=sv*wu; acc2[i]+=sv*ws; }
    }
    #pragma unroll
    for (int i=0;i<8;i++){
        g_us[(nb+i)*128 + w] = acc1[i]*IS128;
        out_sc[(size_t)(nb+i)*512 + w] = acc2[i]*IS128;
    }

    // vector channels: uv, sc_v  (per cartesian component)
    for (int c=0;c<3;c++){
        #pragma unroll
        for (int i=0;i<8;i++){acc1[i]=0.f;acc2[i]=0.f;}
        for (int k=0;k<128;k++){
            float wu = Wuv[k*128+w], ws = Wsv[k*128+w];
            #pragma unroll
            for (int i=0;i<8;i++){ float vv=v8[i][k*3+c]; acc1[i]+=vv*wu; acc2[i]+=vv*ws; }
        }
        #pragma unroll
        for (int i=0;i<8;i++){
            g_uv[(nb+i)*384 + w*3 + c] = acc1[i]*IS128;
            out_sc[(size_t)(nb+i)*512 + 128 + w*3 + c] = acc2[i]*IS128;
        }
    }

    // attr embeddings
    #pragma unroll
    for (int i=0;i<8;i++){acc1[i]=0.f;acc2[i]=0.f;}
    for (int k=0;k<10;k++){
        float w1 = Wsrc[k*128+w], w2 = Wtgt[k*128+w];
        #pragma unroll
        for (int i=0;i<8;i++){ float av=a8[i][k]; acc1[i]+=av*w1; acc2[i]+=av*w2; }
    }
    #pragma unroll
    for (int i=0;i<8;i++){
        g_src[(nb+i)*128+w] = acc1[i]*IS10;
        g_tgt[(nb+i)*128+w] = acc2[i]*IS10;
    }
}

// ---------------- K2: edge layer0 + density branch ----------------
__global__ __launch_bounds__(256) void k2_edge_l0(
    const float* __restrict__ edge_feats,
    const int* __restrict__ snd, const int* __restrict__ rcv,
    const float* __restrict__ Wr0, const float* __restrict__ Wd0,
    const float* __restrict__ Wd1)
{
    __shared__ float ef[32][265];
    __shared__ float dtile[32][65];
    __shared__ int s_snd[32], s_rcv[32];
    int eb = blockIdx.x*32;
    int tid = threadIdx.x;
    if (tid < 32){ s_snd[tid]=snd[eb+tid]; s_rcv[tid]=rcv[eb+tid]; }
    __syncthreads();
    for (int idx=tid; idx<32*264; idx+=256){
        int e = idx/264, k = idx - e*264;
        float v;
        if (k<8)        v = edge_feats[(size_t)(eb+e)*8 + k];
        else if (k<136) v = g_src[s_snd[e]*128 + (k-8)];
        else            v = g_tgt[s_rcv[e]*128 + (k-136)];
        ef[e][k]=v;
    }
    __syncthreads();
    int o = tid & 63, g = tid >> 6;
    float accH[8], accD[8];
    #pragma unroll
    for (int i=0;i<8;i++){accH[i]=0.f;accD[i]=0.f;}
    for (int k=0;k<264;k++){
        float wh = Wr0[k*64+o], wd = Wd0[k*64+o];
        #pragma unroll
        for (int i=0;i<8;i++){ float ev = ef[g*8+i][k]; accH[i]+=ev*wh; accD[i]+=ev*wd; }
    }
    #pragma unroll
    for (int i=0;i<8;i++){
        int e = g*8+i;
        g_hA[(size_t)(eb+e)*64 + o] = siluf(accH[i]*IS264);
        dtile[e][o] = siluf(accD[i]*IS264);
    }
    __syncthreads();
    if (tid < 32){
        float acc=0.f;
        for (int k=0;k<64;k++) acc += dtile[tid][k]*Wd1[k];
        acc *= INV8;
        atomicAdd(&g_density[s_rcv[tid]], tanhf(acc*acc));
    }
}

// ---------------- K3: two fused hidden layers (hA -> smem -> hB) ----------------
__global__ __launch_bounds__(256) void k3_hidden2(
    const float* __restrict__ W1, const float* __restrict__ W2)
{
    __shared__ float ht[32][65];
    __shared__ float hm[32][65];
    int eb = blockIdx.x*32;
    int tid = threadIdx.x;
    for (int idx=tid; idx<32*64; idx+=256) ht[idx>>6][idx&63] = g_hA[(size_t)eb*64 + idx];
    __syncthreads();
    int o = tid&63, g = tid>>6;
    float acc[8];
    #pragma unroll
    for (int i=0;i<8;i++) acc[i]=0.f;
    for (int k=0;k<64;k++){
        float wv = W1[k*64+o];
        #pragma unroll
        for (int i=0;i<8;i++) acc[i] += ht[g*8+i][k]*wv;
    }
    #pragma unroll
    for (int i=0;i<8;i++) hm[g*8+i][o] = siluf(acc[i]*INV8);
    __syncthreads();
    #pragma unroll
    for (int i=0;i<8;i++) acc[i]=0.f;
    for (int k=0;k<64;k++){
        float wv = W2[k*64+o];
        #pragma unroll
        for (int i=0;i<8;i++) acc[i] += hm[g*8+i][k]*wv;
    }
    #pragma unroll
    for (int i=0;i<8;i++) g_hB[(size_t)(eb+g*8+i)*64 + o] = siluf(acc[i]*INV8);
}

// ---------------- K5: tpw + messages + scatter (32 edges / 512 thr) ----------------
__global__ __launch_bounds__(512) void k5_msg(
    const float* __restrict__ edge_attrs,
    const int* __restrict__ snd, const int* __restrict__ rcv,
    const float* __restrict__ Wr3)
{
    __shared__ float ht[32][65];
    __shared__ float y[32][4];
    __shared__ int s_snd[32], s_rcv[32];
    int eb = blockIdx.x*32;
    int tid = threadIdx.x;
    for (int idx=tid; idx<32*64; idx+=512) ht[idx>>6][idx&63] = g_hB[(size_t)eb*64 + idx];
    if (tid<128) y[tid>>2][tid&3] = edge_attrs[(size_t)eb*4 + tid];
    if (tid<32){ s_snd[tid]=snd[eb+tid]; s_rcv[tid]=rcv[eb+tid]; }
    __syncthreads();
    int w = tid & 127, g = tid >> 7;   // 4 groups x 8 edges
    float a1[8],a2[8],a3[8],a4[8];
    #pragma unroll
    for (int i=0;i<8;i++){a1[i]=0.f;a2[i]=0.f;a3[i]=0.f;a4[i]=0.f;}
    for (int k=0;k<64;k++){
        const float* wr = Wr3 + k*512 + w;
        float w1v=wr[0], w2v=wr[128], w3v=wr[256], w4v=wr[384];
        #pragma unroll
        for (int i=0;i<8;i++){
            float hv = ht[g*8+i][k];
            a1[i]+=hv*w1v; a2[i]+=hv*w2v; a3[i]+=hv*w3v; a4[i]+=hv*w4v;
        }
    }
    #pragma unroll
    for (int i=0;i<8;i++){
        int e = g*8+i;
        int sn = s_snd[e], rc = s_rcv[e];
        float xs  = g_us[sn*128+w];
        float xv0 = g_uv[sn*384 + w*3 + 0];
        float xv1 = g_uv[sn*384 + w*3 + 1];
        float xv2 = g_uv[sn*384 + w*3 + 2];
        float y0=y[e][0], ya=y[e][1], yb=y[e][2], yc=y[e][3];
        float w1=a1[i]*INV8, w2=a2[i]*INV8, w3=a3[i]*INV8, w4=a4[i]*INV8;
        float m0a = w1*xs*y0;
        float dv  = xv0*ya + xv1*yb + xv2*yc;
        float m0b = w4*dv*INV_SQRT3;
        atomicAdd(&g_msgs[rc*256 + w],        m0a);
        atomicAdd(&g_msgs[rc*256 + 128 + w],  m0b);
        float t2 = w2*xs*INV_SQRT3;
        float t3 = w3*y0*INV_SQRT3;
        float* pv = &g_msgv[rc*768 + w*3];
        atomicAdd(pv+0,     t2*ya);
        atomicAdd(pv+1,     t2*yb);
        atomicAdd(pv+2,     t2*yc);
        atomicAdd(pv+384+0, t3*xv0);
        atomicAdd(pv+384+1, t3*xv1);
        atomicAdd(pv+384+2, t3*xv2);
    }
}

// ---------------- K6: node finalize ----------------
__global__ __launch_bounds__(256) void k6_node_out(
    const float* __restrict__ W1s, const float* __restrict__ W1v,
    const float* __restrict__ Wrs, const float* __restrict__ Wrv,
    const float* __restrict__ W2s, const float* __restrict__ W2v,
    const float* __restrict__ alpha, const float* __restrict__ beta,
    float* __restrict__ out)
{
    __shared__ float ms[4][256];
    __shared__ float mv[4][768];
    __shared__ float su[4][128];
    __shared__ float uvv[4][384];
    __shared__ float rs[4][256];
    __shared__ float rv[4][384];
    __shared__ float sden[4];
    int nb = blockIdx.x*4;
    int tid = threadIdx.x;
    for (int idx=tid; idx<4*256; idx+=256) ms[idx>>8][idx&255]   = g_msgs[nb*256+idx];
    for (int idx=tid; idx<4*768; idx+=256) mv[idx/768][idx%768]  = g_msgv[nb*768+idx];
    for (int idx=tid; idx<4*128; idx+=256) su[idx>>7][idx&127]   = g_us[nb*128+idx];
    for (int idx=tid; idx<4*384; idx+=256) uvv[idx/384][idx%384] = g_uv[nb*384+idx];
    if (tid<4) sden[tid] = g_density[nb+tid]*beta[0] + alpha[0];
    __syncthreads();

    // m_s = msg_s@W1_s/16/denom + us@Wres_s/sqrt(128)
    {
        int j = tid;
        float acc[4]={0,0,0,0}, accr[4]={0,0,0,0};
        for (int k=0;k<256;k++){
            float wv = W1s[k*256+j];
            #pragma unroll
            for (int i=0;i<4;i++) acc[i]+=ms[i][k]*wv;
        }
        for (int k=0;k<128;k++){
            float wv = Wrs[k*256+j];
            #pragma unroll
            for (int i=0;i<4;i++) accr[i]+=su[i][k]*wv;
        }
        #pragma unroll
        for (int i=0;i<4;i++) rs[i][j] = acc[i]*IS256/sden[i] + accr[i]*IS128;
    }
    // m_v = einsum(msg_v,W1_v)/16/denom + einsum(uv,Wres_v)/sqrt(128)
    int w = tid&127, half = tid>>7;
    {
        float av[2][3], ar[2][3];
        #pragma unroll
        for (int i=0;i<2;i++){ av[i][0]=av[i][1]=av[i][2]=0.f; ar[i][0]=ar[i][1]=ar[i][2]=0.f; }
        for (int k=0;k<256;k++){
            float wv = W1v[k*128+w];
            #pragma unroll
            for (int i=0;i<2;i++){
                #pragma unroll
                for (int c=0;c<3;c++) av[i][c]+= mv[2*half+i][k*3+c]*wv;
            }
        }
        for (int k=0;k<128;k++){
            float wv = Wrv[k*128+w];
            #pragma unroll
            for (int i=0;i<2;i++){
                #pragma unroll
                for (int c=0;c<3;c++) ar[i][c]+= uvv[2*half+i][k*3+c]*wv;
            }
        }
        #pragma unroll
        for (int i=0;i<2;i++){
            #pragma unroll
            for (int c=0;c<3;c++)
                rv[2*half+i][w*3+c] = av[i][c]*IS256/sden[2*half+i] + ar[i][c]*IS128;
        }
    }
    __syncthreads();
    // nonlinearities on m_s: first 128 -> silu, last 128 -> sigmoid (gate)
    {
        int j = tid;
        #pragma unroll
        for (int i=0;i<4;i++){
            float x = rs[i][j];
            float sg = sigmf(x);
            rs[i][j] = (j<128) ? x*sg : sg;
        }
    }
    __syncthreads();
    // gate vectors
    for (int idx=tid; idx<4*384; idx+=256){
        int i = idx/384, r = idx%384;
        rv[i][r] *= rs[i][128 + r/3];
    }
    __syncthreads();
    // final projections
    {
        float fs[2]={0,0};
        float fv[2][3];
        fv[0][0]=fv[0][1]=fv[0][2]=0.f; fv[1][0]=fv[1][1]=fv[1][2]=0.f;
        for (int k=0;k<128;k++){
            float w2s = W2s[k*128+w];
            float w2v = W2v[k*128+w];
            #pragma unroll
            for (int i=0;i<2;i++){
                fs[i]+= rs[2*half+i][k]*w2s;
                #pragma unroll
                for (int c=0;c<3;c++) fv[i][c]+= rv[2*half+i][k*3+c]*w2v;
            }
        }
        #pragma unroll
        for (int i=0;i<2;i++){
            int n = nb + 2*half + i;
            float4 o4;
            o4.x = fs[i]*IS128;
            o4.y = fv[i][0]*IS128;
            o4.z = fv[i][1]*IS128;
            o4.w = fv[i][2]*IS128;
            ((float4*)out)[(size_t)n*128 + w] = o4;
        }
    }
}

// ---------------- launch ----------------
extern "C" void kernel_launch(void* const* d_in, const int* in_sizes, int n_in,
                              void* d_out, int out_size)
{
    const float* node_attrs = (const float*)d_in[0];
    const float* node_feats = (const float*)d_in[1];
    const float* edge_attrs = (const float*)d_in[2];
    const float* edge_feats = (const float*)d_in[3];
    const int*   eidx       = (const int*)d_in[4];
    const int* snd = eidx;
    const int* rcv = eidx + NE;
    const float* Wss  = (const float*)d_in[5];
    const float* Wsv  = (const float*)d_in[6];
    const float* Wus  = (const float*)d_in[7];
    const float* Wuv  = (const float*)d_in[8];
    const float* Wsrc = (const float*)d_in[9];
    const float* Wtgt = (const float*)d_in[10];
    const float* Wr0  = (const float*)d_in[11];
    const float* Wr1  = (const float*)d_in[12];
    const float* Wr2  = (const float*)d_in[13];
    const float* Wr3  = (const float*)d_in[14];
    const float* Wd0  = (const float*)d_in[15];
    const float* Wd1  = (const float*)d_in[16];
    const float* W1s  = (const float*)d_in[17];
    const float* W1v  = (const float*)d_in[18];
    const float* Wrs  = (const float*)d_in[19];
    const float* Wrv  = (const float*)d_in[20];
    const float* W2s  = (const float*)d_in[21];
    const float* W2v  = (const float*)d_in[22];
    const float* alpha= (const float*)d_in[23];
    const float* beta = (const float*)d_in[24];

    float* out = (float*)d_out;
    float* out_sc = out + (size_t)NN*512;   // second tuple element

    k0_zero<<<32800, 256>>>();
    k1_node_prep<<<NN/8, 128>>>(node_attrs, node_feats, Wss, Wsv, Wus, Wuv, Wsrc, Wtgt, out_sc);
    k2_edge_l0<<<NE/32, 256>>>(edge_feats, snd, rcv, Wr0, Wd0, Wd1);
    k3_hidden2<<<NE/32, 256>>>(Wr1, Wr2);   // hA -> (smem) -> hB
    k5_msg<<<NE/32, 512>>>(edge_attrs, snd, rcv, Wr3);
    k6_node_out<<<NN/4, 256>>>(W1s, W1v, Wrs, Wrv, W2s, W2v, alpha, beta, out);
}